// round 13
// baseline (speedup 1.0000x reference)
#include <cuda_runtime.h>
#include <cuda_bf16.h>
#include <cuda_fp16.h>
#include <cstdint>

// B=4, N=4096 tok/batch, d_qk=128, d_v=256.
// Reference reshapes are flat reinterprets of TOKEN-major projection buffers:
// pq[c][n] = q_flat[c*4096+n]  =>  attention channel c = tok>>5 (qk) / tok>>4 (v),
// attention pos n mixes (tok & 31/15) with proj channel pc.
//
// Round-13 (vs 272.7us):
//  * flash: per-iteration __syncthreads() replaced by a 4-deep K/V buffer
//    ring with per-warp mbarrier empty-arrivals. Warps drift up to ~3 tiles,
//    so one warp's serial softmax overlaps the partner warp's MMA phase on
//    the same SMSP (profile showed tensor=35%, occ=12.6%, latency-bound).
//    Numerics, MMA counts, layouts unchanged => rel_err must stay 4.534e-4.
//  * gemm/preps identical to round 12 (epilogue writes flash images directly).

#define NTOK  4096
#define DQK   128
#define DV    256
#define BATCH 4
#define BM    128
#define BN    32
#define NKT   (NTOK / BN)
#define LDQF  136     // Q image row stride (q dim), [ch=128][q=128]
#define LDK   40      // K image row stride (key dim), [ch=128][key=32]
#define LDV   40      // V image row stride (key dim), [ch=256][key=32]

// -------- device scratch (no allocations allowed) --------
__device__ __align__(16) __half g_xhi[4 * BATCH * NTOK * 72];
__device__ __align__(16) __half g_whi[4 * 512 * 72];
__device__ float g_bias[512];
__device__ __align__(16) __half g_qimg[BATCH * 32 * 128 * LDQF];    // [b,qt][ch][q]
__device__ __align__(16) __half g_kimg[BATCH * 128 * 128 * LDK];    // [b,kt][ch][key]
__device__ __align__(16) __half g_vimg[BATCH * 128 * DV * LDV];     // [b,kt][ch][key]

// ---------------- wrappers ----------------
__device__ __forceinline__ uint32_t smem_u32(const void* p) {
    uint32_t a;
    asm("{ .reg .u64 t; cvta.to.shared.u64 t, %1; cvt.u32.u64 %0, t; }" : "=r"(a) : "l"(p));
    return a;
}
__device__ __forceinline__ void ldsm_x4(uint32_t* r, uint32_t saddr) {
    asm volatile("ldmatrix.sync.aligned.m8n8.x4.shared.b16 {%0,%1,%2,%3}, [%4];"
        : "=r"(r[0]), "=r"(r[1]), "=r"(r[2]), "=r"(r[3]) : "r"(saddr));
}
__device__ __forceinline__ void ldsm_x4_t(uint32_t* r, uint32_t saddr) {
    asm volatile("ldmatrix.sync.aligned.m8n8.x4.trans.shared.b16 {%0,%1,%2,%3}, [%4];"
        : "=r"(r[0]), "=r"(r[1]), "=r"(r[2]), "=r"(r[3]) : "r"(saddr));
}
__device__ __forceinline__ void mma_f16(float* d, const uint32_t* a, const uint32_t* b) {
    asm volatile("mma.sync.aligned.m16n8k16.row.col.f32.f16.f16.f32 "
        "{%0,%1,%2,%3}, {%4,%5,%6,%7}, {%8,%9}, {%0,%1,%2,%3};"
        : "+f"(d[0]), "+f"(d[1]), "+f"(d[2]), "+f"(d[3])
        : "r"(a[0]), "r"(a[1]), "r"(a[2]), "r"(a[3]), "r"(b[0]), "r"(b[1]));
}
__device__ __forceinline__ uint32_t packh2(__half x, __half y) {
    __half2 t; t.x = x; t.y = y;
    return *reinterpret_cast<uint32_t*>(&t);
}
__device__ __forceinline__ void bulk_cp(uint32_t dst, const void* src,
                                        uint32_t bytes, uint32_t mbar) {
    asm volatile(
        "cp.async.bulk.shared::cta.global.mbarrier::complete_tx::bytes [%0], [%1], %2, [%3];"
        :: "r"(dst), "l"(src), "r"(bytes), "r"(mbar) : "memory");
}
__device__ __forceinline__ void expect_tx(uint32_t mbar, uint32_t bytes) {
    asm volatile("mbarrier.arrive.expect_tx.shared.b64 _, [%0], %1;"
        :: "r"(mbar), "r"(bytes) : "memory");
}
#define MBARRIER_INIT(mbar, cnt) \
    asm volatile("mbarrier.init.shared.b64 [%0], %1;" :: "r"((uint32_t)(mbar)), "r"((uint32_t)(cnt)) : "memory")
#define MBARRIER_ARRIVE(mbar) \
    asm volatile("mbarrier.arrive.shared.b64 _, [%0];" :: "r"((uint32_t)(mbar)) : "memory")
#define MBARRIER_WAIT_PARITY(mbar, parity) do { \
    uint32_t _m = (uint32_t)(mbar); uint32_t _p = (uint32_t)(parity); uint32_t _d; \
    asm volatile("{\n\t.reg .pred p;\n\t" \
        "mbarrier.try_wait.parity.acquire.cta.shared::cta.b64 p, [%1], %2;\n\t" \
        "selp.b32 %0, 1, 0, p;\n\t}" : "=r"(_d) : "r"(_m), "r"(_p) : "memory"); \
    if (!_d) { \
        asm volatile("{\n\t.reg .pred P1;\n\t" \
            "WL_%=:\n\t" \
            "mbarrier.try_wait.parity.acquire.cta.shared::cta.b64 P1, [%0], %1, 0x989680;\n\t" \
            "@P1 bra.uni WD_%=;\n\t" \
            "bra.uni WL_%=;\n\t" \
            "WD_%=:\n\t}" :: "r"(_m), "r"(_p) : "memory"); \
    } } while (0)

// ---------------- prep_x: x fp32 -> fp16 padded k-step image ----------------
__global__ __launch_bounds__(256) void prep_x_kernel(const float* __restrict__ x) {
    size_t i = (size_t)blockIdx.x * 256 + threadIdx.x;
    int c = (int)(i & 255);
    size_t n = i >> 8;
    size_t off = ((size_t)(c >> 6) * (BATCH * NTOK) + n) * 72 + (c & 63);
    g_xhi[off] = __float2half_rn(x[i]);
}

// ---------------- prep_w: transpose weights -> fp16, concat bias ----------------
__global__ __launch_bounds__(256) void prep_w_kernel(
    const float* __restrict__ Wq, const float* __restrict__ bq,
    const float* __restrict__ Wk, const float* __restrict__ bk,
    const float* __restrict__ Wv, const float* __restrict__ bv)
{
    const int d = blockIdx.x, c = threadIdx.x;
    float w;
    if (d < 128)      w = Wq[c * 128 + d];
    else if (d < 256) w = Wk[c * 128 + (d - 128)];
    else              w = Wv[c * 256 + (d - 256)];
    size_t off = ((size_t)(c >> 6) * 512 + d) * 72 + (c & 63);
    g_whi[off] = __float2half_rn(w);
    if (c == 0)
        g_bias[d] = (d < 128) ? bq[d] : (d < 256) ? bk[d - 128] : bv[d - 256];
}

// ---------------- projection GEMM, epilogue writes flash images ----------------
#define GLDA 72
#define GSAHI 0
#define GSBHI 9216
#define GMBAR 36864
#define GSM_BYTES 36896

__global__ __launch_bounds__(256, 2) void gemm_tensor_kernel() {
    extern __shared__ __half sg[];
    const uint32_t sb = smem_u32(sg);
    const uint32_t mbar = sb + GMBAR;
    const int t = threadIdx.x, lane = t & 31, wid = t >> 5;
    const int nt = blockIdx.x;
    const int m0 = blockIdx.y * 128;
    const int n0 = nt * 128;
    const int lg = lane >> 3, lr = lane & 7;
    const uint32_t a_base = (uint32_t)((16 * wid + lr + (lg & 1) * 8) * GLDA + (lg >> 1) * 8);
    const uint32_t b_base = (uint32_t)(lr * GLDA + lg * 8);

    if (t == 0) MBARRIER_INIT(mbar, 1);
    __syncthreads();

    float acc[16][4];
#pragma unroll
    for (int nf = 0; nf < 16; nf++)
#pragma unroll
        for (int e = 0; e < 4; e++) acc[nf][e] = 0.f;

    for (int kb = 0; kb < 4; kb++) {
        if (t == 0) {
            expect_tx(mbar, 2 * 18432);
            const size_t aoff = ((size_t)kb * (BATCH * NTOK) + m0) * 72;
            const size_t boff = ((size_t)kb * 512 + n0) * 72;
            bulk_cp(sb + 2 * GSAHI, g_xhi + aoff, 18432, mbar);
            bulk_cp(sb + 2 * GSBHI, g_whi + boff, 18432, mbar);
        }
        MBARRIER_WAIT_PARITY(mbar, kb & 1);
#pragma unroll
        for (int kkp = 0; kkp < 2; kkp++) {
            uint32_t qh0[4], qh1[4];
            ldsm_x4(qh0, sb + 2 * (GSAHI + a_base + 32 * kkp));
            ldsm_x4(qh1, sb + 2 * (GSAHI + a_base + 32 * kkp + 16));
#pragma unroll
            for (int nf = 0; nf < 16; nf++) {
                uint32_t bh[4];
                ldsm_x4(bh, sb + 2 * (GSBHI + b_base + nf * 8 * GLDA + 32 * kkp));
                mma_f16(acc[nf], qh0, bh);
                mma_f16(acc[nf], qh1, bh + 2);
            }
        }
        __syncthreads();
    }

    // ---- epilogue: +bias, round fp16, write flash images directly ----
    const int lq = 2 * (lane & 3);
    const int rr0 = m0 + 16 * wid + (lane >> 2);
#pragma unroll
    for (int rowp = 0; rowp < 2; rowp++) {
        const int tok = rr0 + 8 * rowp;
        const int b   = tok >> 12;
        const int tt  = tok & 4095;
        if (nt == 0) {
            __half* dst = g_qimg
                + ((size_t)(b * 32 + (tt & 31)) * 128 + (tt >> 5)) * LDQF;
#pragma unroll
            for (int nf = 0; nf < 16; nf++) {
                const int pc = nf * 8 + lq;
                const float b0 = g_bias[n0 + pc], b1 = g_bias[n0 + pc + 1];
                *(uint32_t*)(dst + pc) = packh2(
                    __float2half_rn(acc[nf][2 * rowp] + b0),
                    __float2half_rn(acc[nf][2 * rowp + 1] + b1));
            }
        } else if (nt == 1) {
            const int ktb = (tt & 31) * 4;
            const int ch  = tt >> 5;
#pragma unroll
            for (int nf = 0; nf < 16; nf++) {
                const int pc = nf * 8 + lq;
                const float b0 = g_bias[n0 + pc], b1 = g_bias[n0 + pc + 1];
                __half* dst = g_kimg
                    + ((size_t)(b * 128 + ktb + (nf >> 2)) * 128 + ch) * LDK
                    + ((nf & 3) * 8 + lq);
                *(uint32_t*)dst = packh2(
                    __float2half_rn(acc[nf][2 * rowp] + b0),
                    __float2half_rn(acc[nf][2 * rowp + 1] + b1));
            }
        } else {
            const int ktb = (tt & 15) * 8 + (nt - 2) * 4;
            const int ch  = tt >> 4;
#pragma unroll
            for (int nf = 0; nf < 16; nf++) {
                const int pc = nf * 8 + lq;
                const float b0 = g_bias[n0 + pc], b1 = g_bias[n0 + pc + 1];
                __half* dst = g_vimg
                    + ((size_t)(b * 128 + ktb + (nf >> 2)) * DV + ch) * LDV
                    + ((nf & 3) * 8 + lq);
                *(uint32_t*)dst = packh2(
                    __float2half_rn(acc[nf][2 * rowp] + b0),
                    __float2half_rn(acc[nf][2 * rowp + 1] + b1));
            }
        }
    }
}

// ---------------- flash kernel (4-deep ring, warp-desynchronized) ----------------
// smem (halves): Q[128ch x 136]@0 (17408), K ring @17408 (4x5120),
// V ring @37888 (4x10240) -> 78848 halves = 157696 B.
// bytes: mbars @157696 (full[s]@+16s, empty[s]@+16s+8), lrow @157760.
#define NS   4
#define SQHI 0
#define SK0  17408
#define SV0  37888
#define KBUF 5120
#define VBUF 10240
#define MBAR_OFF 157696
#define LROW_OFF 157760
#define OSM_LD 132
#define SM_BYTES 158272
#define TILE_BYTES (2 * KBUF + 2 * VBUF)   // 30720 bytes

__global__ __launch_bounds__(256, 1) void flash_kernel(
    const float* __restrict__ xin, const float* __restrict__ gamma_p,
    float* __restrict__ yout)
{
    extern __shared__ __half sm[];
    const uint32_t sb = smem_u32(sm);
    const int t = threadIdx.x, lane = t & 31, wid = t >> 5;
    const int qt = blockIdx.x, b = blockIdx.y;
    const int n0 = qt * BM;
    const int lg = lane >> 3, lr = lane & 7;
    const uint32_t qa_base = (uint32_t)((lr + (lg >> 1) * 8) * LDQF
                                        + 16 * wid + (lg & 1) * 8);
    const uint32_t kb_base = (uint32_t)((lr + lg * 8) * LDK);
    const uint32_t vb_base = (uint32_t)(lr * LDV + lg * 8);

    const __half* kimg = g_kimg + (size_t)b * 128 * (size_t)(128 * LDK);
    const __half* vimg = g_vimg + (size_t)b * 128 * (size_t)(DV * LDV);

    if (t == 0) {
#pragma unroll
        for (int s = 0; s < NS; s++) {
            MBARRIER_INIT(sb + MBAR_OFF + 16 * s, 1);       // full
            MBARRIER_INIT(sb + MBAR_OFF + 16 * s + 8, 8);   // empty (8 warps)
        }
    }
    __syncthreads();
    if (t == 0) {
        // prologue: Q rides on full[0]; stages 0..3 get tiles 0..3
        expect_tx(sb + MBAR_OFF, TILE_BYTES + 2 * 128 * LDQF);
        bulk_cp(sb, g_qimg + (size_t)(b * 32 + qt) * (128 * LDQF),
                2 * 128 * LDQF, sb + MBAR_OFF);
        bulk_cp(sb + 2 * SK0, kimg, 2 * KBUF, sb + MBAR_OFF);
        bulk_cp(sb + 2 * SV0, vimg, 2 * VBUF, sb + MBAR_OFF);
#pragma unroll
        for (int s = 1; s < NS; s++) {
            expect_tx(sb + MBAR_OFF + 16 * s, TILE_BYTES);
            bulk_cp(sb + 2 * (SK0 + s * KBUF), kimg + (size_t)s * KBUF,
                    2 * KBUF, sb + MBAR_OFF + 16 * s);
            bulk_cp(sb + 2 * (SV0 + s * VBUF), vimg + (size_t)s * VBUF,
                    2 * VBUF, sb + MBAR_OFF + 16 * s);
        }
    }

    float oacc[32][4];
#pragma unroll
    for (int nf = 0; nf < 32; nf++)
#pragma unroll
        for (int e = 0; e < 4; e++) oacc[nf][e] = 0.f;
    float lsum0 = 0.f, lsum1 = 0.f;
    float m0 = -1e30f, m1 = -1e30f;

    for (int kt = 0; kt < NKT; kt++) {
        const int s = kt & (NS - 1);
        const int ph = (kt >> 2) & 1;
        const uint32_t fullb = sb + MBAR_OFF + 16 * s;
        const uint32_t emptyb = fullb + 8;
        MBARRIER_WAIT_PARITY(fullb, ph);

        const uint32_t khi = SK0 + s * KBUF;
        const uint32_t vhi = SV0 + s * VBUF;

        // ---- S = Q K^T (single-term fp16, trans operand loads) ----
        float sa[4][4], sc[4][4];
#pragma unroll
        for (int nn = 0; nn < 4; nn++)
#pragma unroll
            for (int e = 0; e < 4; e++) { sa[nn][e] = 0.f; sc[nn][e] = 0.f; }
#pragma unroll
        for (int kkp = 0; kkp < 4; kkp++) {
            uint32_t qh0[4], qh1[4];
            ldsm_x4_t(qh0, sb + 2 * (SQHI + qa_base + (32 * kkp) * LDQF));
            ldsm_x4_t(qh1, sb + 2 * (SQHI + qa_base + (32 * kkp + 16) * LDQF));
#pragma unroll
            for (int nn = 0; nn < 4; nn++) {
                uint32_t kh[4];
                ldsm_x4_t(kh, sb + 2 * (khi + kb_base + (32 * kkp) * LDK + nn * 8));
                mma_f16(sa[nn], qh0, kh);
                mma_f16(sc[nn], qh1, kh + 2);
            }
        }

        // ---- online softmax with running max ----
        float sv[4][4];
#pragma unroll
        for (int nn = 0; nn < 4; nn++)
#pragma unroll
            for (int e = 0; e < 4; e++) sv[nn][e] = sa[nn][e] + sc[nn][e];

        float tm0 = -1e30f, tm1 = -1e30f;
#pragma unroll
        for (int nn = 0; nn < 4; nn++) {
            tm0 = fmaxf(tm0, fmaxf(sv[nn][0], sv[nn][1]));
            tm1 = fmaxf(tm1, fmaxf(sv[nn][2], sv[nn][3]));
        }
        tm0 = fmaxf(tm0, __shfl_xor_sync(0xffffffffu, tm0, 1));
        tm0 = fmaxf(tm0, __shfl_xor_sync(0xffffffffu, tm0, 2));
        tm1 = fmaxf(tm1, __shfl_xor_sync(0xffffffffu, tm1, 1));
        tm1 = fmaxf(tm1, __shfl_xor_sync(0xffffffffu, tm1, 2));
        const float mn0 = fmaxf(m0, tm0), mn1 = fmaxf(m1, tm1);
        const float sc0 = __expf(m0 - mn0), sc1 = __expf(m1 - mn1);
        m0 = mn0; m1 = mn1;
        if (sc0 < 1.f) {
            lsum0 *= sc0;
#pragma unroll
            for (int nf = 0; nf < 32; nf++) { oacc[nf][0] *= sc0; oacc[nf][1] *= sc0; }
        }
        if (sc1 < 1.f) {
            lsum1 *= sc1;
#pragma unroll
            for (int nf = 0; nf < 32; nf++) { oacc[nf][2] *= sc1; oacc[nf][3] *= sc1; }
        }

        uint32_t phi[2][4];
#pragma unroll
        for (int kk = 0; kk < 2; kk++)
#pragma unroll
            for (int half = 0; half < 2; half++) {
                const float* p = sv[2 * kk + half];
                __half h0 = __float2half_rn(__expf(p[0] - mn0));
                __half h1 = __float2half_rn(__expf(p[1] - mn0));
                __half h2 = __float2half_rn(__expf(p[2] - mn1));
                __half h3 = __float2half_rn(__expf(p[3] - mn1));
                phi[kk][2 * half + 0] = packh2(h0, h1);
                phi[kk][2 * half + 1] = packh2(h2, h3);
                lsum0 += __half2float(h0) + __half2float(h1);
                lsum1 += __half2float(h2) + __half2float(h3);
            }

        // ---- O += P V (single-term fp16), all 256 channels ----
#pragma unroll
        for (int nf = 0; nf < 32; nf++) {
            uint32_t vh[4];
            ldsm_x4(vh, sb + 2 * (vhi + vb_base + nf * 8 * LDV));
            mma_f16(oacc[nf], phi[0], vh);
            mma_f16(oacc[nf], phi[1], vh + 2);
        }

        // ---- done with this stage: per-warp arrive; t0 refills when empty ----
        if (lane == 0) MBARRIER_ARRIVE(emptyb);
        if (t == 0 && kt + NS < NKT) {
            MBARRIER_WAIT_PARITY(emptyb, ph);   // all 8 warps done with stage s
            expect_tx(fullb, TILE_BYTES);
            bulk_cp(sb + 2 * khi, kimg + (size_t)(kt + NS) * KBUF, 2 * KBUF, fullb);
            bulk_cp(sb + 2 * vhi, vimg + (size_t)(kt + NS) * VBUF, 2 * VBUF, fullb);
        }
    }

    // ---- epilogue: all warps must finish before smem reuse ----
    __syncthreads();
    lsum0 += __shfl_xor_sync(0xffffffffu, lsum0, 1);
    lsum0 += __shfl_xor_sync(0xffffffffu, lsum0, 2);
    lsum1 += __shfl_xor_sync(0xffffffffu, lsum1, 1);
    lsum1 += __shfl_xor_sync(0xffffffffu, lsum1, 2);
    float* Osm = (float*)sm;
    float* lrow = (float*)((char*)sm + LROW_OFF);
    const int rloc = 16 * wid + (lane >> 2);
    if ((lane & 3) == 0) { lrow[rloc] = lsum0; lrow[rloc + 8] = lsum1; }
#pragma unroll
    for (int nf = 0; nf < 32; nf++) {
        const int c = nf * 8 + 2 * (lane & 3);
        Osm[c * OSM_LD + rloc] = oacc[nf][0];
        Osm[(c + 1) * OSM_LD + rloc] = oacc[nf][1];
        Osm[c * OSM_LD + rloc + 8] = oacc[nf][2];
        Osm[(c + 1) * OSM_LD + rloc + 8] = oacc[nf][3];
    }
    __syncthreads();
    if (t < 128) lrow[t] = gamma_p[0] / lrow[t];
    __syncthreads();
    const float* xb = xin  + (size_t)b * DV * NTOK;
    float*       yb = yout + (size_t)b * DV * NTOK;
    for (int i = t; i < 256 * 32; i += 256) {
        const int c = i >> 5, nn = (i & 31) << 2;
        float4 o = *(float4*)&Osm[c * OSM_LD + nn];
        size_t gi = (size_t)c * NTOK + n0 + nn;
        float4 xv = *(const float4*)(xb + gi);
        float4 y;
        y.x = o.x * lrow[nn + 0] + xv.x;
        y.y = o.y * lrow[nn + 1] + xv.y;
        y.z = o.z * lrow[nn + 2] + xv.z;
        y.w = o.w * lrow[nn + 3] + xv.w;
        *(float4*)(yb + gi) = y;
    }
}

// ---------------- launch ----------------
extern "C" void kernel_launch(void* const* d_in, const int* in_sizes, int n_in,
                              void* d_out, int out_size)
{
    const float* x     = (const float*)d_in[0];
    const float* Wq    = (const float*)d_in[1];
    const float* bq    = (const float*)d_in[2];
    const float* Wk    = (const float*)d_in[3];
    const float* bk    = (const float*)d_in[4];
    const float* Wv    = (const float*)d_in[5];
    const float* bv    = (const float*)d_in[6];
    const float* gamma = (const float*)d_in[7];
    float* out = (float*)d_out;

    prep_x_kernel<<<BATCH * NTOK, 256>>>(x);
    prep_w_kernel<<<512, 256>>>(Wq, bq, Wk, bk, Wv, bv);

    cudaFuncSetAttribute(gemm_tensor_kernel,
                         cudaFuncAttributeMaxDynamicSharedMemorySize, GSM_BYTES);
    gemm_tensor_kernel<<<dim3(4, BATCH * NTOK / 128), 256, GSM_BYTES>>>();

    cudaFuncSetAttribute(flash_kernel,
                         cudaFuncAttributeMaxDynamicSharedMemorySize, SM_BYTES);
    flash_kernel<<<dim3(NTOK / BM, BATCH), 256, SM_BYTES>>>(x, gamma, out);
}

// round 14
// speedup vs baseline: 1.3087x; 1.3087x over previous
#include <cuda_runtime.h>
#include <cuda_bf16.h>
#include <cuda_fp16.h>
#include <cstdint>

// B=4, N=4096 tok/batch, d_qk=128, d_v=256.
// Reference reshapes are flat reinterprets of TOKEN-major projection buffers:
// pq[c][n] = q_flat[c*4096+n]  =>  attention channel c = tok>>5 (qk) / tok>>4 (v),
// attention pos n mixes (tok & 31/15) with proj channel pc.
//
// Round-14 (vs 272.7us best; round-13 ring REVERTED as a regression):
//  * flash: BM=64, 128 threads, __launch_bounds__(128,2) => 2 CTAs/SM
//    (255 regs x 128 thr = half the RF), 4 warps/SMSP. Same per-warp work,
//    same proven R12 double-buffer + __syncthreads pipeline. Latency hiding
//    now comes from occupancy instead of intra-CTA warp drift.
//  * Q images become 64-query tiles: qt=(tt&31)*2+(pc>>6), q=pc&63 (gemm
//    epilogue mapping updated accordingly). K/V images unchanged.
//  * Numerics identical => rel_err must stay 4.534e-4.

#define NTOK  4096
#define DQK   128
#define DV    256
#define BATCH 4
#define BM    64
#define BN    32
#define NKT   (NTOK / BN)
#define LDQF  72      // Q image row stride (q dim), [ch=128][q=64]
#define LDK   40      // K image row stride (key dim), [ch=128][key=32]
#define LDV   40      // V image row stride (key dim), [ch=256][key=32]

// -------- device scratch (no allocations allowed) --------
__device__ __align__(16) __half g_xhi[4 * BATCH * NTOK * 72];
__device__ __align__(16) __half g_whi[4 * 512 * 72];
__device__ float g_bias[512];
__device__ __align__(16) __half g_qimg[BATCH * 64 * 128 * LDQF];    // [b,qt][ch][q]
__device__ __align__(16) __half g_kimg[BATCH * 128 * 128 * LDK];    // [b,kt][ch][key]
__device__ __align__(16) __half g_vimg[BATCH * 128 * DV * LDV];     // [b,kt][ch][key]

// ---------------- wrappers ----------------
__device__ __forceinline__ uint32_t smem_u32(const void* p) {
    uint32_t a;
    asm("{ .reg .u64 t; cvta.to.shared.u64 t, %1; cvt.u32.u64 %0, t; }" : "=r"(a) : "l"(p));
    return a;
}
__device__ __forceinline__ void ldsm_x4(uint32_t* r, uint32_t saddr) {
    asm volatile("ldmatrix.sync.aligned.m8n8.x4.shared.b16 {%0,%1,%2,%3}, [%4];"
        : "=r"(r[0]), "=r"(r[1]), "=r"(r[2]), "=r"(r[3]) : "r"(saddr));
}
__device__ __forceinline__ void ldsm_x4_t(uint32_t* r, uint32_t saddr) {
    asm volatile("ldmatrix.sync.aligned.m8n8.x4.trans.shared.b16 {%0,%1,%2,%3}, [%4];"
        : "=r"(r[0]), "=r"(r[1]), "=r"(r[2]), "=r"(r[3]) : "r"(saddr));
}
__device__ __forceinline__ void mma_f16(float* d, const uint32_t* a, const uint32_t* b) {
    asm volatile("mma.sync.aligned.m16n8k16.row.col.f32.f16.f16.f32 "
        "{%0,%1,%2,%3}, {%4,%5,%6,%7}, {%8,%9}, {%0,%1,%2,%3};"
        : "+f"(d[0]), "+f"(d[1]), "+f"(d[2]), "+f"(d[3])
        : "r"(a[0]), "r"(a[1]), "r"(a[2]), "r"(a[3]), "r"(b[0]), "r"(b[1]));
}
__device__ __forceinline__ uint32_t packh2(__half x, __half y) {
    __half2 t; t.x = x; t.y = y;
    return *reinterpret_cast<uint32_t*>(&t);
}
__device__ __forceinline__ void bulk_cp(uint32_t dst, const void* src,
                                        uint32_t bytes, uint32_t mbar) {
    asm volatile(
        "cp.async.bulk.shared::cta.global.mbarrier::complete_tx::bytes [%0], [%1], %2, [%3];"
        :: "r"(dst), "l"(src), "r"(bytes), "r"(mbar) : "memory");
}
__device__ __forceinline__ void expect_tx(uint32_t mbar, uint32_t bytes) {
    asm volatile("mbarrier.arrive.expect_tx.shared.b64 _, [%0], %1;"
        :: "r"(mbar), "r"(bytes) : "memory");
}
#define MBARRIER_INIT(mbar, cnt) \
    asm volatile("mbarrier.init.shared.b64 [%0], %1;" :: "r"((uint32_t)(mbar)), "r"((uint32_t)(cnt)) : "memory")
#define MBARRIER_WAIT_PARITY(mbar, parity) do { \
    uint32_t _m = (uint32_t)(mbar); uint32_t _p = (uint32_t)(parity); uint32_t _d; \
    asm volatile("{\n\t.reg .pred p;\n\t" \
        "mbarrier.try_wait.parity.acquire.cta.shared::cta.b64 p, [%1], %2;\n\t" \
        "selp.b32 %0, 1, 0, p;\n\t}" : "=r"(_d) : "r"(_m), "r"(_p) : "memory"); \
    if (!_d) { \
        asm volatile("{\n\t.reg .pred P1;\n\t" \
            "WL_%=:\n\t" \
            "mbarrier.try_wait.parity.acquire.cta.shared::cta.b64 P1, [%0], %1, 0x989680;\n\t" \
            "@P1 bra.uni WD_%=;\n\t" \
            "bra.uni WL_%=;\n\t" \
            "WD_%=:\n\t}" :: "r"(_m), "r"(_p) : "memory"); \
    } } while (0)

// ---------------- prep_x: x fp32 -> fp16 padded k-step image ----------------
__global__ __launch_bounds__(256) void prep_x_kernel(const float* __restrict__ x) {
    size_t i = (size_t)blockIdx.x * 256 + threadIdx.x;
    int c = (int)(i & 255);
    size_t n = i >> 8;
    size_t off = ((size_t)(c >> 6) * (BATCH * NTOK) + n) * 72 + (c & 63);
    g_xhi[off] = __float2half_rn(x[i]);
}

// ---------------- prep_w: transpose weights -> fp16, concat bias ----------------
__global__ __launch_bounds__(256) void prep_w_kernel(
    const float* __restrict__ Wq, const float* __restrict__ bq,
    const float* __restrict__ Wk, const float* __restrict__ bk,
    const float* __restrict__ Wv, const float* __restrict__ bv)
{
    const int d = blockIdx.x, c = threadIdx.x;
    float w;
    if (d < 128)      w = Wq[c * 128 + d];
    else if (d < 256) w = Wk[c * 128 + (d - 128)];
    else              w = Wv[c * 256 + (d - 256)];
    size_t off = ((size_t)(c >> 6) * 512 + d) * 72 + (c & 63);
    g_whi[off] = __float2half_rn(w);
    if (c == 0)
        g_bias[d] = (d < 128) ? bq[d] : (d < 256) ? bk[d - 128] : bv[d - 256];
}

// ---------------- projection GEMM, epilogue writes flash images ----------------
#define GLDA 72
#define GSAHI 0
#define GSBHI 9216
#define GMBAR 36864
#define GSM_BYTES 36896

__global__ __launch_bounds__(256, 2) void gemm_tensor_kernel() {
    extern __shared__ __half sg[];
    const uint32_t sb = smem_u32(sg);
    const uint32_t mbar = sb + GMBAR;
    const int t = threadIdx.x, lane = t & 31, wid = t >> 5;
    const int nt = blockIdx.x;
    const int m0 = blockIdx.y * 128;
    const int n0 = nt * 128;
    const int lg = lane >> 3, lr = lane & 7;
    const uint32_t a_base = (uint32_t)((16 * wid + lr + (lg & 1) * 8) * GLDA + (lg >> 1) * 8);
    const uint32_t b_base = (uint32_t)(lr * GLDA + lg * 8);

    if (t == 0) MBARRIER_INIT(mbar, 1);
    __syncthreads();

    float acc[16][4];
#pragma unroll
    for (int nf = 0; nf < 16; nf++)
#pragma unroll
        for (int e = 0; e < 4; e++) acc[nf][e] = 0.f;

    for (int kb = 0; kb < 4; kb++) {
        if (t == 0) {
            expect_tx(mbar, 2 * 18432);
            const size_t aoff = ((size_t)kb * (BATCH * NTOK) + m0) * 72;
            const size_t boff = ((size_t)kb * 512 + n0) * 72;
            bulk_cp(sb + 2 * GSAHI, g_xhi + aoff, 18432, mbar);
            bulk_cp(sb + 2 * GSBHI, g_whi + boff, 18432, mbar);
        }
        MBARRIER_WAIT_PARITY(mbar, kb & 1);
#pragma unroll
        for (int kkp = 0; kkp < 2; kkp++) {
            uint32_t qh0[4], qh1[4];
            ldsm_x4(qh0, sb + 2 * (GSAHI + a_base + 32 * kkp));
            ldsm_x4(qh1, sb + 2 * (GSAHI + a_base + 32 * kkp + 16));
#pragma unroll
            for (int nf = 0; nf < 16; nf++) {
                uint32_t bh[4];
                ldsm_x4(bh, sb + 2 * (GSBHI + b_base + nf * 8 * GLDA + 32 * kkp));
                mma_f16(acc[nf], qh0, bh);
                mma_f16(acc[nf], qh1, bh + 2);
            }
        }
        __syncthreads();
    }

    // ---- epilogue: +bias, round fp16, write flash images directly ----
    const int lq = 2 * (lane & 3);
    const int rr0 = m0 + 16 * wid + (lane >> 2);
#pragma unroll
    for (int rowp = 0; rowp < 2; rowp++) {
        const int tok = rr0 + 8 * rowp;
        const int b   = tok >> 12;
        const int tt  = tok & 4095;
        if (nt == 0) {
            // Q (64-q tiles): qt = (tt&31)*2 + (pc>>6), q = pc&63, ch = tt>>5
            const int qtb = (tt & 31) * 2;
            const int ch  = tt >> 5;
#pragma unroll
            for (int nf = 0; nf < 16; nf++) {
                const int pc = nf * 8 + lq;
                const float b0 = g_bias[n0 + pc], b1 = g_bias[n0 + pc + 1];
                __half* dst = g_qimg
                    + ((size_t)(b * 64 + qtb + (nf >> 3)) * 128 + ch) * LDQF
                    + (pc & 63);
                *(uint32_t*)dst = packh2(
                    __float2half_rn(acc[nf][2 * rowp] + b0),
                    __float2half_rn(acc[nf][2 * rowp + 1] + b1));
            }
        } else if (nt == 1) {
            // K: kt = (tt&31)*4 + (pc>>5), key = pc&31, ch = tt>>5
            const int ktb = (tt & 31) * 4;
            const int ch  = tt >> 5;
#pragma unroll
            for (int nf = 0; nf < 16; nf++) {
                const int pc = nf * 8 + lq;
                const float b0 = g_bias[n0 + pc], b1 = g_bias[n0 + pc + 1];
                __half* dst = g_kimg
                    + ((size_t)(b * 128 + ktb + (nf >> 2)) * 128 + ch) * LDK
                    + ((nf & 3) * 8 + lq);
                *(uint32_t*)dst = packh2(
                    __float2half_rn(acc[nf][2 * rowp] + b0),
                    __float2half_rn(acc[nf][2 * rowp + 1] + b1));
            }
        } else {
            // V: kt = (tt&15)*8 + (pc_full>>5), key = pc_full&31, ch = tt>>4
            const int ktb = (tt & 15) * 8 + (nt - 2) * 4;
            const int ch  = tt >> 4;
#pragma unroll
            for (int nf = 0; nf < 16; nf++) {
                const int pc = nf * 8 + lq;
                const float b0 = g_bias[n0 + pc], b1 = g_bias[n0 + pc + 1];
                __half* dst = g_vimg
                    + ((size_t)(b * 128 + ktb + (nf >> 2)) * DV + ch) * LDV
                    + ((nf & 3) * 8 + lq);
                *(uint32_t*)dst = packh2(
                    __float2half_rn(acc[nf][2 * rowp] + b0),
                    __float2half_rn(acc[nf][2 * rowp + 1] + b1));
            }
        }
    }
}

// ---------------- flash kernel (BM=64, 128 threads, 2 CTAs/SM) ----------------
// smem (halves): Q[128ch x 72]@0 (9216), K bufs @9216 (2x5120),
// V bufs @19456 (2x10240) -> 39936 halves = 79872 B.
// bytes: mbars @79872, lrow @79936. epilogue Osm reuses [0, 256*68*4=69632).
#define SQHI 0
#define SK0  9216
#define SV0  19456
#define KBUF 5120
#define VBUF 10240
#define MBAR_OFF 79872
#define LROW_OFF 79936
#define OSM_LD 68
#define SM_BYTES 80448
#define TILE_BYTES (2 * KBUF + 2 * VBUF)   // 30720 bytes

__global__ __launch_bounds__(128, 2) void flash_kernel(
    const float* __restrict__ xin, const float* __restrict__ gamma_p,
    float* __restrict__ yout)
{
    extern __shared__ __half sm[];
    const uint32_t sb = smem_u32(sm);
    const uint32_t mb0 = sb + MBAR_OFF, mb1 = sb + MBAR_OFF + 8;
    const int t = threadIdx.x, lane = t & 31, wid = t >> 5;   // wid < 4
    const int qt = blockIdx.x, b = blockIdx.y;
    const int n0 = qt * BM;
    const int lg = lane >> 3, lr = lane & 7;
    const uint32_t qa_base = (uint32_t)((lr + (lg >> 1) * 8) * LDQF
                                        + 16 * wid + (lg & 1) * 8);
    const uint32_t kb_base = (uint32_t)((lr + lg * 8) * LDK);
    const uint32_t vb_base = (uint32_t)(lr * LDV + lg * 8);

    const __half* kimg = g_kimg + (size_t)b * 128 * (size_t)(128 * LDK);
    const __half* vimg = g_vimg + (size_t)b * 128 * (size_t)(DV * LDV);

    if (t == 0) { MBARRIER_INIT(mb0, 1); MBARRIER_INIT(mb1, 1); }
    __syncthreads();
    if (t == 0) {
        expect_tx(mb0, TILE_BYTES + 2 * 128 * LDQF);
        bulk_cp(sb, g_qimg + (size_t)(b * 64 + qt) * (128 * LDQF),
                2 * 128 * LDQF, mb0);
        bulk_cp(sb + 2 * SK0, kimg, 2 * KBUF, mb0);
        bulk_cp(sb + 2 * SV0, vimg, 2 * VBUF, mb0);
        expect_tx(mb1, TILE_BYTES);
        bulk_cp(sb + 2 * (SK0 + KBUF), kimg + KBUF, 2 * KBUF, mb1);
        bulk_cp(sb + 2 * (SV0 + VBUF), vimg + VBUF, 2 * VBUF, mb1);
    }

    float oacc[32][4];
#pragma unroll
    for (int nf = 0; nf < 32; nf++)
#pragma unroll
        for (int e = 0; e < 4; e++) oacc[nf][e] = 0.f;
    float lsum0 = 0.f, lsum1 = 0.f;
    float m0 = -1e30f, m1 = -1e30f;

    for (int kt = 0; kt < NKT; kt++) {
        const int buf = kt & 1;
        MBARRIER_WAIT_PARITY(buf ? mb1 : mb0, (kt >> 1) & 1);

        const uint32_t khi = SK0 + buf * KBUF;
        const uint32_t vhi = SV0 + buf * VBUF;

        // ---- S = Q K^T (single-term fp16, trans operand loads) ----
        float sa[4][4], sc[4][4];
#pragma unroll
        for (int nn = 0; nn < 4; nn++)
#pragma unroll
            for (int e = 0; e < 4; e++) { sa[nn][e] = 0.f; sc[nn][e] = 0.f; }
#pragma unroll
        for (int kkp = 0; kkp < 4; kkp++) {
            uint32_t qh0[4], qh1[4];
            ldsm_x4_t(qh0, sb + 2 * (SQHI + qa_base + (32 * kkp) * LDQF));
            ldsm_x4_t(qh1, sb + 2 * (SQHI + qa_base + (32 * kkp + 16) * LDQF));
#pragma unroll
            for (int nn = 0; nn < 4; nn++) {
                uint32_t kh[4];
                ldsm_x4_t(kh, sb + 2 * (khi + kb_base + (32 * kkp) * LDK + nn * 8));
                mma_f16(sa[nn], qh0, kh);
                mma_f16(sc[nn], qh1, kh + 2);
            }
        }

        // ---- online softmax with running max ----
        float sv[4][4];
#pragma unroll
        for (int nn = 0; nn < 4; nn++)
#pragma unroll
            for (int e = 0; e < 4; e++) sv[nn][e] = sa[nn][e] + sc[nn][e];

        float tm0 = -1e30f, tm1 = -1e30f;
#pragma unroll
        for (int nn = 0; nn < 4; nn++) {
            tm0 = fmaxf(tm0, fmaxf(sv[nn][0], sv[nn][1]));
            tm1 = fmaxf(tm1, fmaxf(sv[nn][2], sv[nn][3]));
        }
        tm0 = fmaxf(tm0, __shfl_xor_sync(0xffffffffu, tm0, 1));
        tm0 = fmaxf(tm0, __shfl_xor_sync(0xffffffffu, tm0, 2));
        tm1 = fmaxf(tm1, __shfl_xor_sync(0xffffffffu, tm1, 1));
        tm1 = fmaxf(tm1, __shfl_xor_sync(0xffffffffu, tm1, 2));
        const float mn0 = fmaxf(m0, tm0), mn1 = fmaxf(m1, tm1);
        const float sc0 = __expf(m0 - mn0), sc1 = __expf(m1 - mn1);
        m0 = mn0; m1 = mn1;
        if (sc0 < 1.f) {
            lsum0 *= sc0;
#pragma unroll
            for (int nf = 0; nf < 32; nf++) { oacc[nf][0] *= sc0; oacc[nf][1] *= sc0; }
        }
        if (sc1 < 1.f) {
            lsum1 *= sc1;
#pragma unroll
            for (int nf = 0; nf < 32; nf++) { oacc[nf][2] *= sc1; oacc[nf][3] *= sc1; }
        }

        uint32_t phi[2][4];
#pragma unroll
        for (int kk = 0; kk < 2; kk++)
#pragma unroll
            for (int half = 0; half < 2; half++) {
                const float* p = sv[2 * kk + half];
                __half h0 = __float2half_rn(__expf(p[0] - mn0));
                __half h1 = __float2half_rn(__expf(p[1] - mn0));
                __half h2 = __float2half_rn(__expf(p[2] - mn1));
                __half h3 = __float2half_rn(__expf(p[3] - mn1));
                phi[kk][2 * half + 0] = packh2(h0, h1);
                phi[kk][2 * half + 1] = packh2(h2, h3);
                lsum0 += __half2float(h0) + __half2float(h1);
                lsum1 += __half2float(h2) + __half2float(h3);
            }

        // ---- O += P V (single-term fp16), all 256 channels ----
#pragma unroll
        for (int nf = 0; nf < 32; nf++) {
            uint32_t vh[4];
            ldsm_x4(vh, sb + 2 * (vhi + vb_base + nf * 8 * LDV));
            mma_f16(oacc[nf], phi[0], vh);
            mma_f16(oacc[nf], phi[1], vh + 2);
        }
        __syncthreads();   // all 4 warps done reading buf before refill
        if (t == 0 && kt + 2 < NKT) {
            const uint32_t mb = buf ? mb1 : mb0;
            expect_tx(mb, TILE_BYTES);
            bulk_cp(sb + 2 * khi, kimg + (size_t)(kt + 2) * KBUF, 2 * KBUF, mb);
            bulk_cp(sb + 2 * vhi, vimg + (size_t)(kt + 2) * VBUF, 2 * VBUF, mb);
        }
    }

    // ---- epilogue: transpose O through smem, y = gamma*(O/l) + x ----
    lsum0 += __shfl_xor_sync(0xffffffffu, lsum0, 1);
    lsum0 += __shfl_xor_sync(0xffffffffu, lsum0, 2);
    lsum1 += __shfl_xor_sync(0xffffffffu, lsum1, 1);
    lsum1 += __shfl_xor_sync(0xffffffffu, lsum1, 2);
    float* Osm = (float*)sm;
    float* lrow = (float*)((char*)sm + LROW_OFF);
    const int rloc = 16 * wid + (lane >> 2);          // 0..63
    if ((lane & 3) == 0) { lrow[rloc] = lsum0; lrow[rloc + 8] = lsum1; }
#pragma unroll
    for (int nf = 0; nf < 32; nf++) {
        const int c = nf * 8 + 2 * (lane & 3);
        Osm[c * OSM_LD + rloc] = oacc[nf][0];
        Osm[(c + 1) * OSM_LD + rloc] = oacc[nf][1];
        Osm[c * OSM_LD + rloc + 8] = oacc[nf][2];
        Osm[(c + 1) * OSM_LD + rloc + 8] = oacc[nf][3];
    }
    __syncthreads();
    if (t < 64) lrow[t] = gamma_p[0] / lrow[t];
    __syncthreads();
    const float* xb = xin  + (size_t)b * DV * NTOK;
    float*       yb = yout + (size_t)b * DV * NTOK;
    for (int i = t; i < 256 * 16; i += 128) {
        const int c = i >> 4, nn = (i & 15) << 2;     // 64 q = 16 float4 per ch
        float4 o = *(float4*)&Osm[c * OSM_LD + nn];
        size_t gi = (size_t)c * NTOK + n0 + nn;
        float4 xv = *(const float4*)(xb + gi);
        float4 y;
        y.x = o.x * lrow[nn + 0] + xv.x;
        y.y = o.y * lrow[nn + 1] + xv.y;
        y.z = o.z * lrow[nn + 2] + xv.z;
        y.w = o.w * lrow[nn + 3] + xv.w;
        *(float4*)(yb + gi) = y;
    }
}

// ---------------- launch ----------------
extern "C" void kernel_launch(void* const* d_in, const int* in_sizes, int n_in,
                              void* d_out, int out_size)
{
    const float* x     = (const float*)d_in[0];
    const float* Wq    = (const float*)d_in[1];
    const float* bq    = (const float*)d_in[2];
    const float* Wk    = (const float*)d_in[3];
    const float* bk    = (const float*)d_in[4];
    const float* Wv    = (const float*)d_in[5];
    const float* bv    = (const float*)d_in[6];
    const float* gamma = (const float*)d_in[7];
    float* out = (float*)d_out;

    prep_x_kernel<<<BATCH * NTOK, 256>>>(x);
    prep_w_kernel<<<512, 256>>>(Wq, bq, Wk, bk, Wv, bv);

    cudaFuncSetAttribute(gemm_tensor_kernel,
                         cudaFuncAttributeMaxDynamicSharedMemorySize, GSM_BYTES);
    gemm_tensor_kernel<<<dim3(4, BATCH * NTOK / 128), 256, GSM_BYTES>>>();

    cudaFuncSetAttribute(flash_kernel,
                         cudaFuncAttributeMaxDynamicSharedMemorySize, SM_BYTES);
    flash_kernel<<<dim3(NTOK / BM, BATCH), 128, SM_BYTES>>>(x, gamma, out);
}